// round 14
// baseline (speedup 1.0000x reference)
#include <cuda_runtime.h>

// S4D diagonal SSM scan — fused chunk-parallel kernel, real-only xs layout.
// B=4, D=128, N=64 complex states, L=1024.
// out = [ all_xs real parts (b,t,d,n): B*L*D*N | ys_real (b,d,t): B*D*L ].
// Conjugate symmetry (exact): x[n+32]=conj(x[n]) => row[i]=xr[i%32];
// y_t = sum_{n<32} 2*Cr_n*xr_n.
//
// Phases 1+2 (per-chunk end states + dA^64 combine): one warp per chunk,
// state = lane (verbatim R12). Phase 3 uses a 4-states-per-lane layout
// (lane l owns states 4*(l&7)..+3; lanes 16-31 run one timestep ahead):
// one STG.128 per warp stores TWO complete 64-float rows, no gather shfls,
// y via 3-shfl butterfly over 8-lane groups (no smem transpose traffic).

#define Dd 128
#define Nn 64
#define Bb 4
#define Ll 1024
#define CH 16
#define T0 64

__global__ __launch_bounds__(512, 3) void s4d_fused_kernel(
    const float* __restrict__ us,          // (B, D, L)
    const float* __restrict__ log_dt,      // (D,)
    const float* __restrict__ log_A_real,  // (D, N/2)
    const float* __restrict__ A_imag,      // (D, N/2)
    const float* __restrict__ B_re,        // (D, N)
    const float* __restrict__ B_im,        // (D, N)
    const float* __restrict__ C_re,        // (D, N/2)
    float* __restrict__ out,
    size_t xs_floats, size_t out_floats)
{
    __shared__ float2 ends[CH][32];
    __shared__ float2 seeds[CH][32];
    __shared__ float  ybuf[CH][T0];

    const int lane = threadIdx.x & 31;
    const int c    = threadIdx.x >> 5;     // chunk / warp id, 0..15
    const int d    = blockIdx.x & (Dd - 1);
    const int b    = blockIdx.x >> 7;

    const float dt = __expf(log_dt[d]);

    // ======== Phases 1+2: state = lane (verbatim R12) ========
    {
        const float Are = -__expf(log_A_real[d * 32 + lane]);
        const float Aim = A_imag[d * 32 + lane];
        const float hr = 0.5f * dt * Are;
        const float hi = 0.5f * dt * Aim;
        const float den_r = 1.0f - hr;
        const float den_i = -hi;
        const float inv = 1.0f / (den_r * den_r + den_i * den_i);
        const float num_r = 1.0f + hr;
        const float dAr = (num_r * den_r + hi * den_i) * inv;
        const float dAi = (hi * den_r - num_r * den_i) * inv;
        const float tr = dt * B_re[d * 64 + lane];
        const float ti = dt * B_im[d * 64 + lane];
        const float dBr = (tr * den_r + ti * den_i) * inv;
        const float dBi = (ti * den_r - tr * den_i) * inv;

        // blocked coefficients: x <- dA^4 x + sum_k dA^(4-k) dB u_k
        const float dA2r = dAr * dAr - dAi * dAi;
        const float dA2i = 2.0f * dAr * dAi;
        const float dA4r = dA2r * dA2r - dA2i * dA2i;
        const float dA4i = 2.0f * dA2r * dA2i;
        const float g3r = dAr * dBr - dAi * dBi;
        const float g3i = dAr * dBi + dAi * dBr;
        const float g2r = dA2r * dBr - dA2i * dBi;
        const float g2i = dA2r * dBi + dA2i * dBr;
        const float g1r = dA2r * g3r - dA2i * g3i;
        const float g1i = dA2r * g3i + dA2i * g3r;

        const float* u = us + (size_t)blockIdx.x * Ll + c * T0;

        float xr = 0.f, xi = 0.f;
#pragma unroll
        for (int h = 0; h < 2; ++h) {
            const float uc = u[h * 32 + lane];
#pragma unroll
            for (int j = 0; j < 8; ++j) {
                const float u1 = __shfl_sync(0xffffffffu, uc, 4 * j);
                const float u2 = __shfl_sync(0xffffffffu, uc, 4 * j + 1);
                const float u3 = __shfl_sync(0xffffffffu, uc, 4 * j + 2);
                const float u4 = __shfl_sync(0xffffffffu, uc, 4 * j + 3);
                const float injr = fmaf(g1r, u1, fmaf(g2r, u2, fmaf(g3r, u3, dBr * u4)));
                const float inji = fmaf(g1i, u1, fmaf(g2i, u2, fmaf(g3i, u3, dBi * u4)));
                const float nr = fmaf(dA4r, xr, fmaf(-dA4i, xi, injr));
                const float ni = fmaf(dA4r, xi, fmaf( dA4i, xr, inji));
                xr = nr; xi = ni;
            }
        }
        ends[c][lane] = make_float2(xr, xi);
        __syncthreads();

        // combine: init_c = sum_{j<c} (dA^64)^(c-1-j) * e_j
        float pr = dA4r, pi = dA4i;
#pragma unroll
        for (int q = 0; q < 4; ++q) {
            const float sr = pr * pr - pi * pi;
            const float si = 2.0f * pr * pi;
            pr = sr; pi = si;
        }
        xr = 0.f; xi = 0.f;
        for (int j = 0; j < c; ++j) {
            const float2 e = ends[j][lane];
            const float nr = fmaf(pr, xr, fmaf(-pi, xi, e.x));
            const float ni = fmaf(pr, xi, fmaf( pi, xr, e.y));
            xr = nr; xi = ni;
        }
        seeds[c][lane] = make_float2(xr, xi);
    }
    __syncwarp();

    // ======== Phase 3: 4-states-per-lane, 2 rows per STG.128 ========
    const int s0 = 4 * (lane & 7);          // first owned state
    const bool hi_half = (lane >= 16);      // runs one timestep ahead

    float Ar[4], Ai[4], Br4[4], Bi4[4], Cc[4], X[4], Y[4];
#pragma unroll
    for (int k = 0; k < 4; ++k) {
        const int s = s0 + k;
        const float Are = -__expf(log_A_real[d * 32 + s]);
        const float Aim = A_imag[d * 32 + s];
        const float hr = 0.5f * dt * Are;
        const float hi = 0.5f * dt * Aim;
        const float den_r = 1.0f - hr;
        const float den_i = -hi;
        const float inv = 1.0f / (den_r * den_r + den_i * den_i);
        const float num_r = 1.0f + hr;
        Ar[k]  = (num_r * den_r + hi * den_i) * inv;
        Ai[k]  = (hi * den_r - num_r * den_i) * inv;
        const float tr = dt * B_re[d * 64 + s];
        const float ti = dt * B_im[d * 64 + s];
        Br4[k] = (tr * den_r + ti * den_i) * inv;
        Bi4[k] = (ti * den_r - tr * den_i) * inv;
        Cc[k]  = 2.0f * C_re[d * 32 + s];
        const float2 sd = seeds[c][s];
        X[k] = sd.x; Y[k] = sd.y;
    }

    const float* u = us + (size_t)blockIdx.x * Ll + c * T0;
    const float uc0 = u[lane];
    const float uc1 = u[32 + lane];

    // pre-advance the odd half by one step with u_0
    {
        const float u0 = __shfl_sync(0xffffffffu, uc0, 0);
        if (hi_half) {
#pragma unroll
            for (int k = 0; k < 4; ++k) {
                const float nr = fmaf(Ar[k], X[k], fmaf(-Ai[k], Y[k], Br4[k] * u0));
                const float ni = fmaf(Ar[k], Y[k], fmaf( Ai[k], X[k], Bi4[k] * u0));
                X[k] = nr; Y[k] = ni;
            }
        }
    }

    const bool xs_ok = (xs_floats >= (size_t)Bb * Ll * Dd * Nn);
    const bool y_ok  = (out_floats >= xs_floats + (size_t)Bb * Dd * Ll);
    float* yb = ybuf[c];
    float* __restrict__ y_out = out + xs_floats + (size_t)blockIdx.x * Ll + c * T0;
    const bool ysel = ((lane & 15) == 0);   // lanes 0, 16 stage y
    const int  yhalf = lane >> 4;

    // float4 index of this lane's slot in its first row (t = hi_half)
    float4* __restrict__ xs4 = reinterpret_cast<float4*>(out);
    size_t idx4 = ((size_t)(b * Ll + c * T0 + (hi_half ? 1 : 0))) * 2048
                + d * 16 + (lane & 15);

#pragma unroll
    for (int i = 0; i < 32; ++i) {
        // update 1: t index = 2i + hi_half (both in the same 32-block)
        {
            const float ureg = (2 * i < 32) ? uc0 : uc1;
            const float ut = __shfl_sync(0xffffffffu, ureg,
                                         (2 * i + (int)hi_half) & 31);
#pragma unroll
            for (int k = 0; k < 4; ++k) {
                const float nr = fmaf(Ar[k], X[k], fmaf(-Ai[k], Y[k], Br4[k] * ut));
                const float ni = fmaf(Ar[k], Y[k], fmaf( Ai[k], X[k], Bi4[k] * ut));
                X[k] = nr; Y[k] = ni;
            }
        }

        // store rows 2i (lanes 0-15) and 2i+1 (lanes 16-31): one STG.128
        if (xs_ok)
            xs4[idx4] = make_float4(X[0], X[1], X[2], X[3]);
        idx4 += 4096;                        // advance 2 timesteps

        // y: 4-FMA partial + 3-shfl butterfly over 8-lane groups
        float p = fmaf(Cc[0], X[0],
                  fmaf(Cc[1], X[1],
                  fmaf(Cc[2], X[2], Cc[3] * X[3])));
        p += __shfl_xor_sync(0xffffffffu, p, 1);
        p += __shfl_xor_sync(0xffffffffu, p, 2);
        p += __shfl_xor_sync(0xffffffffu, p, 4);
        if (ysel) yb[2 * i + yhalf] = p;

        // update 2 (dead after the last stored rows)
        if (i < 31) {
            const int idx2 = 2 * i + 1 + (int)hi_half;
            float ut;
            if (2 * i + 2 <= 31) {
                ut = __shfl_sync(0xffffffffu, uc0, idx2);
            } else if (2 * i + 1 >= 32) {
                ut = __shfl_sync(0xffffffffu, uc1, idx2 & 31);
            } else {   // i == 15: halves straddle the uc0/uc1 boundary
                const float v0 = __shfl_sync(0xffffffffu, uc0, idx2 & 31);
                const float v1 = __shfl_sync(0xffffffffu, uc1, idx2 & 31);
                ut = (idx2 < 32) ? v0 : v1;
            }
#pragma unroll
            for (int k = 0; k < 4; ++k) {
                const float nr = fmaf(Ar[k], X[k], fmaf(-Ai[k], Y[k], Br4[k] * ut));
                const float ni = fmaf(Ar[k], Y[k], fmaf( Ai[k], X[k], Bi4[k] * ut));
                X[k] = nr; Y[k] = ni;
            }
        }
    }

    __syncwarp();
    {
        const float2 v = reinterpret_cast<float2*>(yb)[lane];
        if (y_ok)
            reinterpret_cast<float2*>(y_out)[lane] = v;
    }
}

extern "C" void kernel_launch(void* const* d_in, const int* in_sizes, int n_in,
                              void* d_out, int out_size)
{
    (void)in_sizes; (void)n_in;
    const float* us         = (const float*)d_in[0];
    const float* log_dt     = (const float*)d_in[1];
    const float* log_A_real = (const float*)d_in[2];
    const float* A_imag     = (const float*)d_in[3];
    const float* B_re       = (const float*)d_in[4];
    const float* B_im       = (const float*)d_in[5];
    const float* C_re       = (const float*)d_in[6];
    float* out = (float*)d_out;

    const size_t out_floats = (size_t)out_size;
    const size_t ys_floats  = (size_t)Bb * Dd * Ll;
    const size_t xs_floats  = (out_floats > ys_floats) ? (out_floats - ys_floats) : 0;

    s4d_fused_kernel<<<Bb * Dd, 512>>>(us, log_dt, log_A_real, A_imag,
                                       B_re, B_im, C_re, out,
                                       xs_floats, out_floats);
}

// round 16
// speedup vs baseline: 1.9563x; 1.9563x over previous
#include <cuda_runtime.h>

// S4D diagonal SSM scan — fused chunk-parallel kernel (R11 structure),
// real-only xs layout. B=4, D=128, N=64 complex states, L=1024.
// out = [ all_xs real parts (b,t,d,n): B*L*D*N | ys_real (b,d,t): B*D*L ].
// Conjugate symmetry (exact): x[n+32]=conj(x[n]) => row[i]=xr[i%32];
// y_t = sum_{n<32} 2*Cr_n*xr_n.
//
// One block (512 thr = 16 warps) per (b,d); warp c owns chunk [64c,64c+64).
// Phase 1: 4-step-blocked zero-seeded scan -> end state. Phase 2: combine
// with dA^64. Phase 3: seeded per-step re-scan; u via one LDG.64 + shfl,
// xs via 2 streaming STG.32 with incremental pointer, y via 16-step
// smem transpose reduce (single 32x17 buffer per warp, two syncwarps).

#define Dd 128
#define Nn 64
#define Bb 4
#define Ll 1024
#define CH 16
#define T0 64

__global__ __launch_bounds__(512, 4) void s4d_fused_kernel(
    const float* __restrict__ us,          // (B, D, L)
    const float* __restrict__ log_dt,      // (D,)
    const float* __restrict__ log_A_real,  // (D, N/2)
    const float* __restrict__ A_imag,      // (D, N/2)
    const float* __restrict__ B_re,        // (D, N)
    const float* __restrict__ B_im,        // (D, N)
    const float* __restrict__ C_re,        // (D, N/2)
    float* __restrict__ out,
    size_t xs_floats, size_t out_floats)
{
    __shared__ float2 ends[CH][32];
    __shared__ float  ybuf[CH][32 * 17];   // [lane][step-in-group], pad 17

    const int lane = threadIdx.x & 31;     // state n = lane
    const int c    = threadIdx.x >> 5;     // chunk / warp id, 0..15
    const int d    = blockIdx.x & (Dd - 1);
    const int b    = blockIdx.x >> 7;

    // ---- bilinear discretization for state n = lane ----
    const float dt  = __expf(log_dt[d]);
    const float Are = -__expf(log_A_real[d * 32 + lane]);
    const float Aim = A_imag[d * 32 + lane];
    const float hr = 0.5f * dt * Are;
    const float hi = 0.5f * dt * Aim;
    const float den_r = 1.0f - hr;
    const float den_i = -hi;
    const float inv = 1.0f / (den_r * den_r + den_i * den_i);
    const float num_r = 1.0f + hr;
    const float dAr = (num_r * den_r + hi * den_i) * inv;
    const float dAi = (hi * den_r - num_r * den_i) * inv;
    const float tr = dt * B_re[d * 64 + lane];
    const float ti = dt * B_im[d * 64 + lane];
    const float dBr = (tr * den_r + ti * den_i) * inv;
    const float dBi = (ti * den_r - tr * den_i) * inv;
    const float Cr2 = 2.0f * C_re[d * 32 + lane];

    // one 64-float u chunk per warp as a single LDG.64 (float2 per lane)
    const float2 upair = reinterpret_cast<const float2*>(
        us + (size_t)blockIdx.x * Ll + c * T0)[lane];

    // ---- Phase 1: 4-step-blocked zero-seeded chunk scan ----
    const float dA2r = dAr * dAr - dAi * dAi;
    const float dA2i = 2.0f * dAr * dAi;
    const float dA4r = dA2r * dA2r - dA2i * dA2i;
    const float dA4i = 2.0f * dA2r * dA2i;
    const float g3r = dAr * dBr - dAi * dBi;
    const float g3i = dAr * dBi + dAi * dBr;
    const float g2r = dA2r * dBr - dA2i * dBi;
    const float g2i = dA2r * dBi + dA2i * dBr;
    const float g1r = dA2r * g3r - dA2i * g3i;
    const float g1i = dA2r * g3i + dA2i * g3r;

    float xr = 0.f, xi = 0.f;
#pragma unroll
    for (int j = 0; j < 16; ++j) {
        // steps 4j..4j+3: u at lanes 2j, 2j+1 (x = even t, y = odd t)
        const float u1 = __shfl_sync(0xffffffffu, upair.x, 2 * j);
        const float u2 = __shfl_sync(0xffffffffu, upair.y, 2 * j);
        const float u3 = __shfl_sync(0xffffffffu, upair.x, 2 * j + 1);
        const float u4 = __shfl_sync(0xffffffffu, upair.y, 2 * j + 1);
        const float injr = fmaf(g1r, u1, fmaf(g2r, u2, fmaf(g3r, u3, dBr * u4)));
        const float inji = fmaf(g1i, u1, fmaf(g2i, u2, fmaf(g3i, u3, dBi * u4)));
        const float nr = fmaf(dA4r, xr, fmaf(-dA4i, xi, injr));
        const float ni = fmaf(dA4r, xi, fmaf( dA4i, xr, inji));
        xr = nr; xi = ni;
    }
    ends[c][lane] = make_float2(xr, xi);
    __syncthreads();

    // ---- Phase 2: init_c = sum_{j<c} (dA^64)^(c-1-j) * e_j ----
    {
        float pr = dA4r, pi = dA4i;         // dA^64 via 4 squarings
#pragma unroll
        for (int q = 0; q < 4; ++q) {
            const float sr = pr * pr - pi * pi;
            const float si = 2.0f * pr * pi;
            pr = sr; pi = si;
        }
        xr = 0.f; xi = 0.f;
        for (int j = 0; j < c; ++j) {
            const float2 e = ends[j][lane];
            const float nr = fmaf(pr, xr, fmaf(-pi, xi, e.x));
            const float ni = fmaf(pr, xi, fmaf( pi, xr, e.y));
            xr = nr; xi = ni;
        }
    }

    // ---- Phase 3: seeded per-step re-scan, emit xs + y ----
    const bool xs_ok = (xs_floats >= (size_t)Bb * Ll * Dd * Nn);
    const bool y_ok  = (out_floats >= xs_floats + (size_t)Bb * Dd * Ll);
    float* yb = ybuf[c];
    float* __restrict__ y_out =
        out + xs_floats + (size_t)blockIdx.x * Ll + c * T0;

    // incremental row pointer: row (b, c*T0, d); advance by D*N per step
    float* __restrict__ p =
        out + ((size_t)(b * Ll + c * T0) * Dd + d) * (size_t)Nn;

#pragma unroll
    for (int g = 0; g < 4; ++g) {           // 4 groups of 16 steps
#pragma unroll
        for (int s = 0; s < 16; ++s) {
            const int st = g * 16 + s;      // 0..63
            const float ue = __shfl_sync(0xffffffffu, upair.x, st >> 1);
            const float uo = __shfl_sync(0xffffffffu, upair.y, st >> 1);
            const float ut = (st & 1) ? uo : ue;
            const float nr = fmaf(dAr, xr, fmaf(-dAi, xi, dBr * ut));
            const float ni = fmaf(dAr, xi, fmaf( dAi, xr, dBi * ut));
            xr = nr; xi = ni;

            if (xs_ok) {
                __stcs(p + lane, xr);          // n = lane
                __stcs(p + 32 + lane, xr);     // n = lane+32 (conjugate)
            }
            p += Dd * Nn;

            yb[lane * 17 + s] = Cr2 * xr;
        }
        __syncwarp();
        // transposed reduce: lane pair (l, l+16) sums halves of column l&15
        float acc = 0.f;
        const int col = lane & 15;
        const int hb  = lane & 16;
#pragma unroll
        for (int i = 0; i < 16; ++i)
            acc += yb[(hb + i) * 17 + col];
        acc += __shfl_xor_sync(0xffffffffu, acc, 16);
        if (y_ok && lane < 16)
            y_out[g * 16 + lane] = acc;
        __syncwarp();
    }
}

extern "C" void kernel_launch(void* const* d_in, const int* in_sizes, int n_in,
                              void* d_out, int out_size)
{
    (void)in_sizes; (void)n_in;
    const float* us         = (const float*)d_in[0];
    const float* log_dt     = (const float*)d_in[1];
    const float* log_A_real = (const float*)d_in[2];
    const float* A_imag     = (const float*)d_in[3];
    const float* B_re       = (const float*)d_in[4];
    const float* B_im       = (const float*)d_in[5];
    const float* C_re       = (const float*)d_in[6];
    float* out = (float*)d_out;

    const size_t out_floats = (size_t)out_size;
    const size_t ys_floats  = (size_t)Bb * Dd * Ll;
    const size_t xs_floats  = (out_floats > ys_floats) ? (out_floats - ys_floats) : 0;

    s4d_fused_kernel<<<Bb * Dd, 512>>>(us, log_dt, log_A_real, A_imag,
                                       B_re, B_im, C_re, out,
                                       xs_floats, out_floats);
}